// round 5
// baseline (speedup 1.0000x reference)
#include <cuda_runtime.h>
#include <math.h>

#define BB 32
#define NN 1024
#define FF 10
#define DD 64
#define MM 4
#define RR 8
#define KK 20
#define BN_EPS 1e-5f

// ---------------- scratch (static device arrays; no allocations) ----------------
__device__ float g_h_it [BB*NN*DD];
__device__ float g_xlin [BB*NN*DD];
__device__ float g_eit  [BB*NN];
__device__ float g_si   [BB*NN];
__device__ float g_sj   [BB*NN];
__device__ float g_proto[MM*NN*DD];                 // P_m = e_base + U_m V_m
__device__ float g_gram [(size_t)10*NN*NN];         // 40 MB: 4 diag G_mm + 6 sym H_ml
__device__ int   g_cmb_i[BB*5];                     // {a, b, id_aa, id_bb, id_ab}
__device__ float g_cmb_f[BB*5];                     // {ca, cb, ca^2, cb^2, ca*cb}
__device__ int   g_grp_cnt[10];
__device__ int   g_grp_list[10*BB];
__device__ int   g_needed[10];
__device__ int   g_tidx [BB*NN*KK];
__device__ float g_tw   [BB*NN*KK];
__device__ float g_gnn  [BB*NN*DD];
__device__ float g_part1[128*DD*2];
__device__ float g_part2[128*DD*2];
__device__ float g_scale1[DD], g_shift1[DD], g_scale2[DD], g_shift2[DD];

__device__ const int c_pm[10] = {0,0,0,0,1,1,1,2,2,3};
__device__ const int c_pl[10] = {0,1,2,3,1,2,3,2,3,3};
// upper-triangle tile decode (8x8 tiles, ti<=tj)
__device__ const int c_tti[36] = {0,0,0,0,0,0,0,0, 1,1,1,1,1,1,1, 2,2,2,2,2,2,
                                  3,3,3,3,3, 4,4,4,4, 5,5,5, 6,6, 7};
__device__ const int c_ttj[36] = {0,1,2,3,4,5,6,7, 1,2,3,4,5,6,7, 2,3,4,5,6,7,
                                  3,4,5,6,7, 4,5,6,7, 5,6,7, 6,7, 7};

__device__ __forceinline__ float nanfix(float v) {
    if (isnan(v)) return 0.f;
    if (isinf(v)) return v > 0.f ? 1e4f : -1e4f;
    return v;
}
__device__ __forceinline__ float lrelu(float v) { return v > 0.f ? v : 0.2f * v; }
__device__ __forceinline__ unsigned ordf(float f) {
    unsigned u = __float_as_uint(f);
    return (u & 0x80000000u) ? ~u : (u | 0x80000000u);
}
__device__ __forceinline__ float unordf(unsigned o) {
    unsigned u = (o & 0x80000000u) ? (o & 0x7fffffffu) : ~o;
    return __uint_as_float(u);
}
__device__ __forceinline__ int pidf(int m, int l) { return m*4 + l - (m*(m+1))/2; }

// ---------------- kP: proto P[m] = e_base + U_m V_m ------------------------------
__global__ void __launch_bounds__(256) kP_proto(
    const float* __restrict__ eb, const float* __restrict__ lru,
    const float* __restrict__ lrv)
{
    int m = blockIdx.y, n0 = blockIdx.x * 4;
    __shared__ float sv[RR*DD];
    __shared__ float su[4][RR];
    int tid = threadIdx.x;
    for (int i = tid; i < RR*DD; i += 256) sv[i] = lrv[(size_t)m*RR*DD + i];
    if (tid < 32) {
        int nd = tid >> 3, r = tid & 7;
        su[nd][r] = lru[((size_t)m*NN + n0 + nd)*RR + r];
    }
    __syncthreads();
    int grp = tid >> 6, d = tid & 63;
    int n = n0 + grp;
    float acc = eb[(size_t)n*DD + d];
#pragma unroll
    for (int r = 0; r < RR; r++) acc += su[grp][r] * sv[r*DD + d];
    g_proto[((size_t)m*NN + n)*DD + d] = acc;
}

// ---------------- K1: h_it = data@W_cond+b ; e_it ; x_lin = data@W_gnn ----------
__global__ void __launch_bounds__(256) k1_cond(
    const float* __restrict__ data, const float* __restrict__ Wc,
    const float* __restrict__ bc,   const float* __restrict__ Wap,
    const float* __restrict__ bap,  const float* __restrict__ Wav,
    const float* __restrict__ Wg)
{
    __shared__ float sWc[FF*DD];
    __shared__ float sWap[DD*DD];
    __shared__ float sWg[FF*DD];
    __shared__ float sdata[4][FF];
    __shared__ float sh[4][DD];
    __shared__ float sred[4][2];
    int tid = threadIdx.x;
    for (int i = tid; i < FF*DD; i += 256) { sWc[i] = Wc[i]; sWg[i] = Wg[i]; }
    for (int i = tid; i < DD*DD; i += 256) sWap[i] = Wap[i];
    if (tid < 4*FF) {
        int nd = tid / FF, f = tid % FF;
        int node2 = blockIdx.x * 4 + nd;
        sdata[nd][f] = data[(size_t)node2 * FF + f];
    }
    __syncthreads();
    int grp = tid >> 6, d = tid & 63;
    int node = blockIdx.x * 4 + grp;

    float h = bc[d];
#pragma unroll
    for (int f = 0; f < FF; f++) h += sdata[grp][f] * sWc[f*DD + d];
    sh[grp][d] = h;
    g_h_it[(size_t)node*DD + d] = h;

    float xl = 0.f;
#pragma unroll
    for (int f = 0; f < FF; f++) xl += sdata[grp][f] * sWg[f*DD + d];
    g_xlin[(size_t)node*DD + d] = xl;
    __syncthreads();

    float a = bap[d];
    for (int k = 0; k < DD; k++) a += sh[grp][k] * sWap[k*DD + d];
    a = lrelu(a);
    float ep = a * Wav[d];
    for (int off = 16; off; off >>= 1) ep += __shfl_down_sync(0xffffffffu, ep, off);
    if ((tid & 31) == 0) sred[grp][(tid >> 5) & 1] = ep;
    __syncthreads();
    if (d == 0) g_eit[node] = nanfix(sred[grp][0] + sred[grp][1]);
}

// ---------------- K2: per-batch pool -> h_sys -> gumbel top-2 routing -----------
__global__ void __launch_bounds__(256) k2_pool(
    const float* __restrict__ Wr, const float* __restrict__ br,
    const float* __restrict__ gum, float* __restrict__ dout, int out_size)
{
    int b = blockIdx.x, tid = threadIdx.x;
    __shared__ float se[NN];
    __shared__ float sred[8];
    __shared__ float sval;
    __shared__ float spart[4][DD];
    __shared__ float shsys[DD];

    float lmax = -INFINITY;
    for (int n = tid; n < NN; n += 256) { float v = g_eit[b*NN + n]; se[n] = v; lmax = fmaxf(lmax, v); }
    for (int off = 16; off; off >>= 1) lmax = fmaxf(lmax, __shfl_down_sync(0xffffffffu, lmax, off));
    if ((tid & 31) == 0) sred[tid >> 5] = lmax;
    __syncthreads();
    if (tid == 0) { float m = sred[0]; for (int i = 1; i < 8; i++) m = fmaxf(m, sred[i]); sval = m; }
    __syncthreads();
    float mx = sval;
    __syncthreads();
    float lsum = 0.f;
    for (int n = tid; n < NN; n += 256) { float ev = expf(se[n] - mx); se[n] = ev; lsum += ev; }
    for (int off = 16; off; off >>= 1) lsum += __shfl_down_sync(0xffffffffu, lsum, off);
    if ((tid & 31) == 0) sred[tid >> 5] = lsum;
    __syncthreads();
    if (tid == 0) { float s = 0.f; for (int i = 0; i < 8; i++) s += sred[i]; sval = s; }
    __syncthreads();
    float ssum = sval;

    int d = tid & 63, g = tid >> 6;
    float acc = 0.f;
    const float* hb = g_h_it + (size_t)b*NN*DD;
    for (int n = g*256; n < g*256 + 256; n++) acc += se[n] * hb[(size_t)n*DD + d];
    spart[g][d] = acc;
    __syncthreads();
    if (tid < DD) {
        float hs = (spart[0][tid] + spart[1][tid] + spart[2][tid] + spart[3][tid]) / ssum;
        shsys[tid] = hs;
        if (out_size >= BB*NN + BB*DD) dout[BB*NN + b*DD + tid] = hs;
    }
    __syncthreads();
    if (tid == 0) {
        float lg[MM]; float pmx = -INFINITY;
        for (int m = 0; m < MM; m++) {
            float s = br[m] + gum[b*MM + m];
            for (int k = 0; k < DD; k++) s += shsys[k] * Wr[k*MM + m];
            lg[m] = s;                  // TAU = 1
            pmx = fmaxf(pmx, s);
        }
        float ps = 0.f;
        for (int m = 0; m < MM; m++) { lg[m] = expf(lg[m] - pmx); ps += lg[m]; }
        float pi[MM];
        for (int m = 0; m < MM; m++) {
            pi[m] = lg[m] / ps;
            if (out_size >= BB*NN + BB*DD + BB*MM)
                dout[BB*NN + BB*DD + b*MM + m] = pi[m];
        }
        // top-2 (ties -> smaller index, matching lax.top_k)
        int i1 = 0;
        for (int m = 1; m < MM; m++) if (pi[m] > pi[i1]) i1 = m;
        int i2 = -1;
        for (int m = 0; m < MM; m++) { if (m == i1) continue; if (i2 < 0 || pi[m] > pi[i2]) i2 = m; }
        float hsum = fmaxf(pi[i1] + pi[i2], 1e-12f);
        int a  = i1 < i2 ? i1 : i2;
        int b2 = i1 < i2 ? i2 : i1;
        float ca = pi[a] / hsum, cb = pi[b2] / hsum;
        g_cmb_i[b*5+0] = a;            g_cmb_i[b*5+1] = b2;
        g_cmb_i[b*5+2] = pidf(a, a);   g_cmb_i[b*5+3] = pidf(b2, b2);
        g_cmb_i[b*5+4] = pidf(a, b2);
        g_cmb_f[b*5+0] = ca;   g_cmb_f[b*5+1] = cb;
        g_cmb_f[b*5+2] = ca*ca; g_cmb_f[b*5+3] = cb*cb; g_cmb_f[b*5+4] = ca*cb;
    }
}

// ---------------- kG: group batches by expert pair ; needed-pid mask -------------
__global__ void kG_group()
{
    __shared__ int scnt[10];
    __shared__ int sneed[10];
    int t = threadIdx.x;
    if (t < 10) { scnt[t] = 0; sneed[t] = 0; }
    __syncthreads();
    if (t < BB) {
        int idh = g_cmb_i[t*5+4];
        int slot = atomicAdd(&scnt[idh], 1);
        g_grp_list[idh*BB + slot] = t;
        atomicExch(&sneed[g_cmb_i[t*5+2]], 1);
        atomicExch(&sneed[g_cmb_i[t*5+3]], 1);
        atomicExch(&sneed[idh], 1);
    }
    __syncthreads();
    if (t < 10) { g_grp_cnt[t] = scnt[t]; g_needed[t] = sneed[t]; }
}

// ---------------- K3: mixed = ca*P_a + cb*P_b (not stored) ; s_i, s_j ------------
__global__ void __launch_bounds__(256) k3_mixed(
    const float* __restrict__ ai, const float* __restrict__ aj,
    const float* __restrict__ aei, const float* __restrict__ aej)
{
    int b = blockIdx.y;
    int n0 = blockIdx.x * 4;
    __shared__ float sred[4][2][2];
    int tid = threadIdx.x;
    int grp = tid >> 6, d = tid & 63;
    int ea = g_cmb_i[b*5+0], eb2 = g_cmb_i[b*5+1];
    float ca = g_cmb_f[b*5+0], cb = g_cmb_f[b*5+1];
    int n = n0 + grp;
    float acc = nanfix(ca * g_proto[((size_t)ea*NN + n)*DD + d]
                     + cb * g_proto[((size_t)eb2*NN + n)*DD + d]);
    size_t idx = ((size_t)b*NN + n)*DD + d;
    float xl = g_xlin[idx];
    float t1 = xl*ai[d] + acc*aei[d];
    float t2 = xl*aj[d] + acc*aej[d];
    for (int off = 16; off; off >>= 1) {
        t1 += __shfl_down_sync(0xffffffffu, t1, off);
        t2 += __shfl_down_sync(0xffffffffu, t2, off);
    }
    if ((tid & 31) == 0) {
        int half = (tid >> 5) & 1;
        sred[grp][half][0] = t1;
        sred[grp][half][1] = t2;
    }
    __syncthreads();
    if (d == 0) {
        g_si[b*NN + n] = sred[grp][0][0] + sred[grp][1][0];
        g_sj[b*NN + n] = sred[grp][0][1] + sred[grp][1][1];
    }
}

// ---------------- kB: symmetric Gram, upper-triangle tiles + mirror --------------
__global__ void __launch_bounds__(256) kB_gram()
{
    int pid = blockIdx.z;
    if (!g_needed[pid]) return;
    extern __shared__ float sm[];
    float* As = sm;                 // [128][65]
    float* Bs = sm + 128*65;        // [64][132]
    int m = c_pm[pid], l = c_pl[pid];
    int ti = c_tti[blockIdx.x], tj = c_ttj[blockIdx.x];
    int i0 = ti * 128, j0 = tj * 128;
    int tid = threadIdx.x;
    int tx = tid & 15, ty = tid >> 4;
    float c[8][8];
#pragma unroll
    for (int r = 0; r < 8; r++)
#pragma unroll
        for (int s = 0; s < 8; s++) c[r][s] = 0.f;

    int npass = (m == l) ? 1 : 2;
    for (int p = 0; p < npass; p++) {
        const float* A  = g_proto + (size_t)(p == 0 ? m : l)*NN*DD;
        const float* Bv = g_proto + (size_t)(p == 0 ? l : m)*NN*DD;
        if (p) __syncthreads();
        for (int idx = tid; idx < 128*64; idx += 256) {
            int i = idx >> 6, k = idx & 63;
            As[i*65 + k] = A[(size_t)(i0 + i)*DD + k];
        }
        for (int idx = tid; idx < 128*64; idx += 256) {
            int j = idx >> 6, k = idx & 63;
            Bs[k*132 + j] = Bv[(size_t)(j0 + j)*DD + k];
        }
        __syncthreads();
#pragma unroll 8
        for (int k = 0; k < 64; k++) {
            float a[8], bb[8];
#pragma unroll
            for (int r = 0; r < 8; r++) a[r] = As[(ty*8 + r)*65 + k];
            float4 b0 = *(const float4*)&Bs[k*132 + tx*8];
            float4 b1 = *(const float4*)&Bs[k*132 + tx*8 + 4];
            bb[0]=b0.x; bb[1]=b0.y; bb[2]=b0.z; bb[3]=b0.w;
            bb[4]=b1.x; bb[5]=b1.y; bb[6]=b1.z; bb[7]=b1.w;
#pragma unroll
            for (int r = 0; r < 8; r++)
#pragma unroll
                for (int s = 0; s < 8; s++) c[r][s] += a[r] * bb[s];
        }
    }
    float* G = g_gram + (size_t)pid*NN*NN;
    // straight tile (i0, j0)
#pragma unroll
    for (int r = 0; r < 8; r++) {
        float* dst = G + (size_t)(i0 + ty*8 + r)*NN + j0 + tx*8;
        ((float4*)dst)[0] = make_float4(c[r][0], c[r][1], c[r][2], c[r][3]);
        ((float4*)dst)[1] = make_float4(c[r][4], c[r][5], c[r][6], c[r][7]);
    }
    if (ti != tj) {
        // mirror tile (j0, i0) = transpose, via smem stage [128][129]
        __syncthreads();
        float* stg = sm;
#pragma unroll
        for (int r = 0; r < 8; r++)
#pragma unroll
            for (int s = 0; s < 8; s++)
                stg[(ty*8 + r)*129 + tx*8 + s] = c[r][s];
        __syncthreads();
        int w = tid >> 5, lane = tid & 31;
        for (int rr = 0; rr < 16; rr++) {
            int jj = w*16 + rr;
            float* dst = G + (size_t)(j0 + jj)*NN + i0;
#pragma unroll
            for (int c2 = 0; c2 < 4; c2++) {
                int ii = lane + 32*c2;
                dst[ii] = stg[ii*129 + jj];
            }
        }
    }
}

// ---------------- kC: pair-grouped combine + exact top-20 + softmax --------------
__global__ void __launch_bounds__(256) kC_topk()
{
    int pid = blockIdx.y;
    __shared__ int scntS;
    __shared__ int slist[BB];
    __shared__ float scf[BB][3];
    int tid = threadIdx.x;
    if (tid == 0) scntS = g_grp_cnt[pid];
    __syncthreads();
    int cnt = scntS;
    if (cnt == 0) return;
    if (tid < cnt) {
        int b = g_grp_list[pid*BB + tid];
        slist[tid] = b;
        scf[tid][0] = g_cmb_f[b*5+2];
        scf[tid][1] = g_cmb_f[b*5+3];
        scf[tid][2] = g_cmb_f[b*5+4];
    }
    __syncthreads();
    int m = c_pm[pid], l = c_pl[pid];
    int ida = pidf(m, m), idb = pidf(l, l);
    int w = tid >> 5, lane = tid & 31;
    int i = blockIdx.x * 8 + w;
    const float* ga = g_gram + ((size_t)ida << 20) + ((size_t)i << 10);
    const float* gb = g_gram + ((size_t)idb << 20) + ((size_t)i << 10);
    const float* gh = g_gram + ((size_t)pid << 20) + ((size_t)i << 10);

    // lane owns 32 values: n = 128*cc + 4*lane + q
    float x[32], y[32], z[32];
#pragma unroll
    for (int cc = 0; cc < 8; cc++) {
        int off = cc*128 + lane*4;
        float4 t0 = *(const float4*)(ga + off);
        float4 t1 = *(const float4*)(gb + off);
        float4 t2 = *(const float4*)(gh + off);
        x[cc*4+0]=t0.x; x[cc*4+1]=t0.y; x[cc*4+2]=t0.z; x[cc*4+3]=t0.w;
        y[cc*4+0]=t1.x; y[cc*4+1]=t1.y; y[cc*4+2]=t1.z; y[cc*4+3]=t1.w;
        z[cc*4+0]=t2.x; z[cc*4+1]=t2.y; z[cc*4+2]=t2.z; z[cc*4+3]=t2.w;
    }

    for (int q = 0; q < cnt; q++) {
        float caa = scf[q][0], cbb = scf[q][1], cab = scf[q][2];
        unsigned ov[32];
#pragma unroll
        for (int e = 0; e < 32; e++)
            ov[e] = ordf(nanfix(caa*x[e] + cbb*y[e] + cab*z[e]));
        // 4 groups of 8; ascending scan + strict '>' keeps smallest index on ties
        unsigned gm[4]; int gi[4];
#pragma unroll
        for (int g = 0; g < 4; g++) {
            unsigned bm = 0; int bi = g*8;
#pragma unroll
            for (int q2 = 0; q2 < 8; q2++) {
                int li = g*8 + q2;
                if (ov[li] > bm) { bm = ov[li]; bi = li; }
            }
            gm[g] = bm; gi[g] = bi;
        }
        unsigned res_o = 0; int res_n = 0;
#pragma unroll 1
        for (int t = 0; t < KK; t++) {
            unsigned lv = gm[0]; int lg = 0;
            if (gm[1] > lv) { lv = gm[1]; lg = 1; }
            if (gm[2] > lv) { lv = gm[2]; lg = 2; }
            if (gm[3] > lv) { lv = gm[3]; lg = 3; }
            int li = (lg == 0) ? gi[0] : (lg == 1) ? gi[1] : (lg == 2) ? gi[2] : gi[3];
            int my_n = ((li >> 2) << 7) + (lane << 2) + (li & 3);
            unsigned wv = __reduce_max_sync(0xffffffffu, lv);
            unsigned cand = (lv == wv) ? (unsigned)my_n : 0xffffffffu;
            unsigned wn = __reduce_min_sync(0xffffffffu, cand);
            if (lane == t) { res_o = wv; res_n = (int)wn; }
            if (lv == wv && (unsigned)my_n == wn) {
#pragma unroll
                for (int g = 0; g < 4; g++) if (lg == g) {
                    unsigned bm = 0; int bi = g*8;
#pragma unroll
                    for (int q2 = 0; q2 < 8; q2++) {
                        int l2 = g*8 + q2;
                        if (l2 == li) ov[l2] = 0;
                        if (ov[l2] > bm) { bm = ov[l2]; bi = l2; }
                    }
                    gm[g] = bm; gi[g] = bi;
                }
            }
        }
        // softmax over the 20 extracted values
        float val = (lane < KK) ? unordf(res_o) : -INFINITY;
        float m2 = val;
        for (int off = 16; off; off >>= 1) m2 = fmaxf(m2, __shfl_xor_sync(0xffffffffu, m2, off));
        float e = (lane < KK) ? expf(val - m2) : 0.f;
        float s2 = e;
        for (int off = 16; off; off >>= 1) s2 += __shfl_xor_sync(0xffffffffu, s2, off);
        if (lane < KK) {
            int b = slist[q];
            size_t row = (size_t)b*NN + i;
            g_tidx[row*KK + lane] = res_n;
            g_tw[row*KK + lane]   = e / s2;
        }
    }
}

// ---------------- K6: GAT edge softmax + weighted aggregation (warp/node) --------
__global__ void __launch_bounds__(256) k6_gat(const float* __restrict__ bgnn)
{
    int tid = threadIdx.x, w = tid >> 5, lane = tid & 31;
    int row = blockIdx.x * 8 + w;
    int b = row >> 10, n = row & (NN - 1);
    float si  = g_si[row];
    float sjn = g_sj[row];
    int idx = 0; float tw = 0.f, alpha = -INFINITY;
    if (lane < KK) {
        idx = g_tidx[(size_t)row*KK + lane];
        tw  = g_tw[(size_t)row*KK + lane];
        float sj = g_sj[b*NN + idx];
        if (idx != n) alpha = lrelu(si + sj);         // self-loop removed
    } else if (lane == KK) {
        alpha = lrelu(si + sjn);                      // re-added self loop
    }
    float m = alpha;
    for (int off = 16; off; off >>= 1) m = fmaxf(m, __shfl_xor_sync(0xffffffffu, m, off));
    float e = (lane <= KK) ? expf(alpha - m) : 0.f;
    float s = e;
    for (int off = 16; off; off >>= 1) s += __shfl_xor_sync(0xffffffffu, s, off);
    float wgt = e / s;
    if (lane < KK) wgt *= tw;

    size_t xb = (size_t)b*NN*DD;
    float ws = __shfl_sync(0xffffffffu, wgt, KK);
    float a0 = ws * g_xlin[(size_t)row*DD + lane];
    float a1 = ws * g_xlin[(size_t)row*DD + lane + 32];
#pragma unroll
    for (int k = 0; k < KK; k++) {
        float wk = __shfl_sync(0xffffffffu, wgt, k);
        int   ik = __shfl_sync(0xffffffffu, idx, k);
        const float* xr = g_xlin + xb + (size_t)ik*DD;
        a0 += wk * xr[lane];
        a1 += wk * xr[lane + 32];
    }
    g_gnn[(size_t)row*DD + lane]      = a0 + bgnn[lane];
    g_gnn[(size_t)row*DD + lane + 32] = a1 + bgnn[lane + 32];
}

// ---------------- K7: partial per-channel stats of g_gnn -------------------------
__global__ void __launch_bounds__(256) k7_stats()
{
    int tid = threadIdx.x, d = tid & 63, g = tid >> 6;
    size_t r0 = (size_t)blockIdx.x * 256 + g * 64;
    float s = 0.f, q = 0.f;
    for (int r = 0; r < 64; r++) {
        float v = g_gnn[(r0 + r)*DD + d];
        s += v; q += v*v;
    }
    __shared__ float ss[4][DD], sq[4][DD];
    ss[g][d] = s; sq[g][d] = q;
    __syncthreads();
    if (tid < DD) {
        g_part1[blockIdx.x*DD*2 + tid]      = ss[0][tid]+ss[1][tid]+ss[2][tid]+ss[3][tid];
        g_part1[blockIdx.x*DD*2 + DD + tid] = sq[0][tid]+sq[1][tid]+sq[2][tid]+sq[3][tid];
    }
}

// ---------------- K8: fold partials -> scale/shift (which: 0 = bn1, 1 = bn_out) --
__global__ void k8_bnparam(int which, const float* __restrict__ gamma,
                           const float* __restrict__ beta)
{
    int d = threadIdx.x;
    if (d >= DD) return;
    const float* part = which ? g_part2 : g_part1;
    float s = 0.f, q = 0.f;
    for (int i = 0; i < 128; i++) {
        s += part[i*DD*2 + d];
        q += part[i*DD*2 + DD + d];
    }
    float inv = 1.f / (float)(BB*NN);
    float mean = s * inv;
    float var  = q * inv - mean*mean;
    float sc = gamma[d] * rsqrtf(var + BN_EPS);
    if (which) { g_scale2[d] = sc; g_shift2[d] = beta[d] - mean*sc; }
    else       { g_scale1[d] = sc; g_shift1[d] = beta[d] - mean*sc; }
}

// ---------------- K9: bn1+relu, *embed -> stats2 only (no store) -----------------
__global__ void __launch_bounds__(256) k9_mid(const float* __restrict__ embed)
{
    int tid = threadIdx.x, d = tid & 63, g = tid >> 6;
    size_t r0 = (size_t)blockIdx.x * 256 + g * 64;
    float sc = g_scale1[d], sh = g_shift1[d];
    float s = 0.f, q = 0.f;
    for (int r = 0; r < 64; r++) {
        size_t row = r0 + r;
        int n = (int)(row & (NN - 1));
        float v = fmaxf(g_gnn[row*DD + d]*sc + sh, 0.f);
        float o = v * embed[(size_t)n*DD + d];
        s += o; q += o*o;
    }
    __shared__ float ss[4][DD], sq[4][DD];
    ss[g][d] = s; sq[g][d] = q;
    __syncthreads();
    if (tid < DD) {
        g_part2[blockIdx.x*DD*2 + tid]      = ss[0][tid]+ss[1][tid]+ss[2][tid]+ss[3][tid];
        g_part2[blockIdx.x*DD*2 + DD + tid] = sq[0][tid]+sq[1][tid]+sq[2][tid]+sq[3][tid];
    }
}

// ---------------- K11: recompute bn1 path, bn_out+relu, @W_out -> out[b,n] -------
__global__ void __launch_bounds__(256) k11_out(
    const float* __restrict__ embed,
    const float* __restrict__ Wout, const float* __restrict__ bout,
    float* __restrict__ dout, int out_size)
{
    int tid = threadIdx.x, w = tid >> 5, lane = tid & 31;
    int row = blockIdx.x * 8 + w;
    int n = row & (NN - 1);
    float o0 = fmaxf(g_gnn[(size_t)row*DD + lane]     *g_scale1[lane]      + g_shift1[lane],      0.f)
               * embed[(size_t)n*DD + lane];
    float o1 = fmaxf(g_gnn[(size_t)row*DD + lane + 32]*g_scale1[lane + 32] + g_shift1[lane + 32], 0.f)
               * embed[(size_t)n*DD + lane + 32];
    float v0 = fmaxf(o0*g_scale2[lane]      + g_shift2[lane],      0.f)*Wout[lane];
    float v1 = fmaxf(o1*g_scale2[lane + 32] + g_shift2[lane + 32], 0.f)*Wout[lane + 32];
    float s = v0 + v1;
    for (int off = 16; off; off >>= 1) s += __shfl_down_sync(0xffffffffu, s, off);
    if (lane == 0 && row < out_size) dout[row] = s + bout[0];
}

// ---------------- launch --------------------------------------------------------
extern "C" void kernel_launch(void* const* d_in, const int* in_sizes, int n_in,
                              void* d_out, int out_size)
{
    const float* data = (const float*)d_in[0];
    const float* gum  = (const float*)d_in[1];
    const float* Wc   = (const float*)d_in[2];
    const float* bc   = (const float*)d_in[3];
    const float* Wap  = (const float*)d_in[4];
    const float* bap  = (const float*)d_in[5];
    const float* Wav  = (const float*)d_in[6];
    const float* Wr   = (const float*)d_in[7];
    const float* br   = (const float*)d_in[8];
    const float* eb   = (const float*)d_in[9];
    const float* lru  = (const float*)d_in[10];
    const float* lrv  = (const float*)d_in[11];
    const float* Wg   = (const float*)d_in[12];
    const float* ai   = (const float*)d_in[13];
    const float* aj   = (const float*)d_in[14];
    const float* aei  = (const float*)d_in[15];
    const float* aej  = (const float*)d_in[16];
    const float* bgnn = (const float*)d_in[17];
    const float* g1   = (const float*)d_in[18];
    const float* be1  = (const float*)d_in[19];
    const float* emb  = (const float*)d_in[20];
    const float* g2   = (const float*)d_in[21];
    const float* be2  = (const float*)d_in[22];
    const float* Wout = (const float*)d_in[23];
    const float* bout = (const float*)d_in[24];
    float* out = (float*)d_out;

    dim3 gp(NN/4, MM);
    kP_proto<<<gp, 256>>>(eb, lru, lrv);
    k1_cond<<<BB*NN/4, 256>>>(data, Wc, bc, Wap, bap, Wav, Wg);
    k2_pool<<<BB, 256>>>(Wr, br, gum, out, out_size);
    kG_group<<<1, 64>>>();
    dim3 g3(NN/4, BB);
    k3_mixed<<<g3, 256>>>(ai, aj, aei, aej);

    const int kb_smem = (128*65 + 64*132) * 4;   // 67072 B (>= 128*129*4 stage)
    cudaFuncSetAttribute((const void*)kB_gram,
                         cudaFuncAttributeMaxDynamicSharedMemorySize, kb_smem);
    dim3 gb(36, 1, 10);
    kB_gram<<<gb, 256, kb_smem>>>();

    dim3 gc(NN/8, 10);
    kC_topk<<<gc, 256>>>();
    k6_gat<<<BB*NN/8, 256>>>(bgnn);
    k7_stats<<<128, 256>>>();
    k8_bnparam<<<1, 64>>>(0, g1, be1);
    k9_mid<<<128, 256>>>(emb);
    k8_bnparam<<<1, 64>>>(1, g2, be2);
    k11_out<<<BB*NN/8, 256>>>(emb, Wout, bout, out, out_size);
}